// round 1
// baseline (speedup 1.0000x reference)
#include <cuda_runtime.h>
#include <cstdint>

#define WS    8
#define MQ    4
#define HEADS 8
#define DIM   256
#define HD    32
#define BATCH 4
#define IMGH  128
#define IMGW  128
#define NWIN  256            // windows per batch (16*16)
#define BW    (BATCH*NWIN)   // 1024 total windows
#define WS2   64             // keys per window
#define NQ    (MQ*WS2)       // 256 queries per window
#define ROWS_Q  (BW*NQ)      // 262144
#define ROWS_KV (BW*WS2)     // 65536

// Scratch (device globals — no allocation allowed)
__device__ float g_q  [ROWS_Q  * DIM];       // 256 MB
__device__ float g_kv [ROWS_KV * 2 * DIM];   // 128 MB
__device__ float g_att[ROWS_Q  * DIM];       // 256 MB

// ---------------------------------------------------------------------------
// Generic fp32 GEMM:  C[M,N] = A[M,K=256] @ W[256,N] + bias[N]
// Tile 128x64, BK=16, 256 threads, 8x4 per-thread microtile.
// ---------------------------------------------------------------------------
__global__ __launch_bounds__(256) void gemm_bias_kernel(
    const float* __restrict__ A, const float* __restrict__ W,
    const float* __restrict__ bias, float* __restrict__ C, int N)
{
    __shared__ float As[128][16];
    __shared__ float Wsm[16][64];
    const int t  = threadIdx.x;
    const int bm = blockIdx.y, bn = blockIdx.x;
    const int arow = t >> 1;
    const int akq  = (t & 1) * 8;
    const int wk   = t >> 4;
    const int wn   = (t & 15) * 4;
    const int tm   = (t >> 4) * 8;
    const int tn   = (t & 15) * 4;

    const float* Arow = A + ((size_t)(bm * 128 + arow)) * DIM;
    const float* Wp0  = W + (size_t)wk * N + bn * 64 + wn;

    float acc[8][4];
    #pragma unroll
    for (int i = 0; i < 8; i++)
        #pragma unroll
        for (int j = 0; j < 4; j++) acc[i][j] = 0.f;

    for (int k0 = 0; k0 < DIM; k0 += 16) {
        float4 a0 = *(const float4*)(Arow + k0 + akq);
        float4 a1 = *(const float4*)(Arow + k0 + akq + 4);
        float4 wv = *(const float4*)(Wp0 + (size_t)k0 * N);
        *(float4*)&As[arow][akq]     = a0;
        *(float4*)&As[arow][akq + 4] = a1;
        *(float4*)&Wsm[wk][wn]       = wv;
        __syncthreads();
        #pragma unroll
        for (int kk = 0; kk < 16; kk++) {
            float4 wr = *(const float4*)&Wsm[kk][tn];
            #pragma unroll
            for (int i = 0; i < 8; i++) {
                float a = As[tm + i][kk];
                acc[i][0] += a * wr.x; acc[i][1] += a * wr.y;
                acc[i][2] += a * wr.z; acc[i][3] += a * wr.w;
            }
        }
        __syncthreads();
    }

    float4 bv = *(const float4*)(bias + bn * 64 + tn);
    #pragma unroll
    for (int i = 0; i < 8; i++) {
        float4 o = make_float4(acc[i][0] + bv.x, acc[i][1] + bv.y,
                               acc[i][2] + bv.z, acc[i][3] + bv.w);
        *(float4*)(C + (size_t)(bm * 128 + tm + i) * N + bn * 64 + tn) = o;
    }
}

// ---------------------------------------------------------------------------
// KV projection with fused window-partition gather:
//   g_kv[r, 0:512] = image_row(r) @ Wkv + bkv
// where r -> (window, pos) -> image pixel (b, wy*8+iy, wx*8+ix).
// ---------------------------------------------------------------------------
__global__ __launch_bounds__(256) void gemm_kv_kernel(
    const float* __restrict__ img, const float* __restrict__ Wkv,
    const float* __restrict__ bkv)
{
    const int N = 2 * DIM;  // 512
    __shared__ float As[128][16];
    __shared__ float Wsm[16][64];
    const int t  = threadIdx.x;
    const int bm = blockIdx.y, bn = blockIdx.x;
    const int arow = t >> 1;
    const int akq  = (t & 1) * 8;
    const int wk   = t >> 4;
    const int wn   = (t & 15) * 4;
    const int tm   = (t >> 4) * 8;
    const int tn   = (t & 15) * 4;

    // gather: row r of the window-partitioned image
    const int r    = bm * 128 + arow;
    const int wwin = r >> 6, p = r & 63;
    const int b    = wwin >> 8, widx = wwin & 255;
    const int wy   = widx >> 4, wx = widx & 15;
    const int py   = wy * 8 + (p >> 3);
    const int px   = wx * 8 + (p & 7);
    const float* Arow = img + (((size_t)b * IMGH + py) * IMGW + px) * DIM;
    const float* Wp0  = Wkv + (size_t)wk * N + bn * 64 + wn;

    float acc[8][4];
    #pragma unroll
    for (int i = 0; i < 8; i++)
        #pragma unroll
        for (int j = 0; j < 4; j++) acc[i][j] = 0.f;

    for (int k0 = 0; k0 < DIM; k0 += 16) {
        float4 a0 = *(const float4*)(Arow + k0 + akq);
        float4 a1 = *(const float4*)(Arow + k0 + akq + 4);
        float4 wv = *(const float4*)(Wp0 + (size_t)k0 * N);
        *(float4*)&As[arow][akq]     = a0;
        *(float4*)&As[arow][akq + 4] = a1;
        *(float4*)&Wsm[wk][wn]       = wv;
        __syncthreads();
        #pragma unroll
        for (int kk = 0; kk < 16; kk++) {
            float4 wr = *(const float4*)&Wsm[kk][tn];
            #pragma unroll
            for (int i = 0; i < 8; i++) {
                float a = As[tm + i][kk];
                acc[i][0] += a * wr.x; acc[i][1] += a * wr.y;
                acc[i][2] += a * wr.z; acc[i][3] += a * wr.w;
            }
        }
        __syncthreads();
    }

    float4 bv = *(const float4*)(bkv + bn * 64 + tn);
    #pragma unroll
    for (int i = 0; i < 8; i++) {
        float4 o = make_float4(acc[i][0] + bv.x, acc[i][1] + bv.y,
                               acc[i][2] + bv.z, acc[i][3] + bv.w);
        *(float4*)(g_kv + (size_t)(bm * 128 + tm + i) * N + bn * 64 + tn) = o;
    }
}

// ---------------------------------------------------------------------------
// Attention: one block per (window, head). 256 threads = 256 queries.
// K,V (64x32) and bias (64x64) in smem; scores kept in registers.
// ---------------------------------------------------------------------------
__global__ __launch_bounds__(256) void attn_kernel(const float* __restrict__ btab)
{
    __shared__ float4 Ks[WS2 * 8];
    __shared__ float4 Vs[WS2 * 8];
    __shared__ float  Bs[WS2][WS2 + 1];  // pad: kill 32-way conflict on Bs[qb][k]

    const int blk = blockIdx.x;
    const int win = blk >> 3;
    const int h   = blk & 7;
    const int t   = threadIdx.x;

    // load K, V for this (window, head)
    {
        const size_t base = (size_t)win * WS2 * (2 * DIM) + h * HD;
        #pragma unroll
        for (int i = 0; i < 2; i++) {
            int idx = t + i * 256;           // 0..511 float4s
            int kr = idx >> 3, dg = idx & 7;
            Ks[idx] = *(const float4*)(g_kv + base + (size_t)kr * 512 + dg * 4);
            Vs[idx] = *(const float4*)(g_kv + base + DIM + (size_t)kr * 512 + dg * 4);
        }
    }
    // relative-position bias for this head
    #pragma unroll
    for (int i = 0; i < 16; i++) {
        int e  = t + i * 256;                // 0..4095
        int qp = e >> 6, kp = e & 63;
        int dr = (qp >> 3) - (kp >> 3) + 7;
        int dc = (qp & 7)  - (kp & 7)  + 7;
        Bs[qp][kp] = btab[(dr * 15 + dc) * HEADS + h];
    }
    __syncthreads();

    const float scale = 0.17677669529663687f;  // 32^-0.5
    float4 q4[8];
    {
        const float* qp = g_q + ((size_t)(win * NQ + t)) * DIM + h * HD;
        #pragma unroll
        for (int j = 0; j < 8; j++) {
            float4 v = *(const float4*)(qp + j * 4);
            v.x *= scale; v.y *= scale; v.z *= scale; v.w *= scale;
            q4[j] = v;
        }
    }

    const int qb = t & 63;  // bias row (tiled over M query groups)
    float s[64];
    float mx = -1e30f;
    #pragma unroll
    for (int k = 0; k < 64; k++) {
        float acc = Bs[qb][k];
        #pragma unroll
        for (int j = 0; j < 8; j++) {
            float4 kv = Ks[k * 8 + j];
            acc += q4[j].x * kv.x + q4[j].y * kv.y + q4[j].z * kv.z + q4[j].w * kv.w;
        }
        s[k] = acc;
        mx = fmaxf(mx, acc);
    }
    float sum = 0.f;
    #pragma unroll
    for (int k = 0; k < 64; k++) { float e = __expf(s[k] - mx); s[k] = e; sum += e; }
    const float inv = 1.f / sum;

    float4 o[8];
    #pragma unroll
    for (int j = 0; j < 8; j++) o[j] = make_float4(0.f, 0.f, 0.f, 0.f);
    #pragma unroll
    for (int k = 0; k < 64; k++) {
        float p = s[k];
        #pragma unroll
        for (int j = 0; j < 8; j++) {
            float4 v = Vs[k * 8 + j];
            o[j].x += p * v.x; o[j].y += p * v.y;
            o[j].z += p * v.z; o[j].w += p * v.w;
        }
    }

    float* op = g_att + ((size_t)(win * NQ + t)) * DIM + h * HD;
    #pragma unroll
    for (int j = 0; j < 8; j++) {
        float4 v = o[j];
        v.x *= inv; v.y *= inv; v.z *= inv; v.w *= inv;
        *(float4*)(op + j * 4) = v;
    }
}

// ---------------------------------------------------------------------------
extern "C" void kernel_launch(void* const* d_in, const int* in_sizes, int n_in,
                              void* d_out, int out_size)
{
    const float* gauss = (const float*)d_in[0];
    const float* img   = (const float*)d_in[1];
    const float* btab  = (const float*)d_in[2];
    const float* Wq    = (const float*)d_in[3];
    const float* bq    = (const float*)d_in[4];
    const float* Wkv   = (const float*)d_in[5];
    const float* bkv   = (const float*)d_in[6];
    const float* Wp    = (const float*)d_in[7];
    const float* bp    = (const float*)d_in[8];
    float* out = (float*)d_out;

    void* pq = nullptr;  cudaGetSymbolAddress(&pq, g_q);
    void* pa = nullptr;  cudaGetSymbolAddress(&pa, g_att);

    // 1) Q projection: [262144,256] @ [256,256] + bq
    gemm_bias_kernel<<<dim3(DIM / 64, ROWS_Q / 128), 256>>>(gauss, Wq, bq, (float*)pq, DIM);
    // 2) KV projection with window gather: [65536,256] @ [256,512] + bkv
    gemm_kv_kernel<<<dim3((2 * DIM) / 64, ROWS_KV / 128), 256>>>(img, Wkv, bkv);
    // 3) Attention per (window, head)
    attn_kernel<<<BW * HEADS, 256>>>(btab);
    // 4) Output projection: [262144,256] @ [256,256] + bp -> d_out
    gemm_bias_kernel<<<dim3(DIM / 64, ROWS_Q / 128), 256>>>((const float*)pa, Wp, bp, out, DIM);
}

// round 3
// speedup vs baseline: 1.5046x; 1.5046x over previous
#include <cuda_runtime.h>
#include <cstdint>

#define WS    8
#define MQ    4
#define HEADS 8
#define DIM   256
#define HD    32
#define BATCH 4
#define IMGH  128
#define IMGW  128
#define NWIN  256            // windows per batch (16*16)
#define BW    (BATCH*NWIN)   // 1024 total windows
#define WS2   64             // keys per window
#define NQ    (MQ*WS2)       // 256 queries per window
#define ROWS_Q  (BW*NQ)      // 262144
#define ROWS_KV (BW*WS2)     // 65536

// Scratch (device globals — no allocation allowed)
__device__ float g_q  [ROWS_Q  * DIM];       // 256 MB
__device__ float g_kv [ROWS_KV * 2 * DIM];   // 128 MB
__device__ float g_att[ROWS_Q  * DIM];       // 256 MB

__device__ __forceinline__ uint32_t f2tf(float x) {
    uint32_t u;
    asm("cvt.rna.tf32.f32 %0, %1;" : "=r"(u) : "f"(x));
    return u;
}

__device__ __forceinline__ void mma_tf32(float c[4],
    uint32_t a0, uint32_t a1, uint32_t a2, uint32_t a3,
    uint32_t b0, uint32_t b1)
{
    asm volatile(
        "mma.sync.aligned.m16n8k8.row.col.f32.tf32.tf32.f32 "
        "{%0,%1,%2,%3}, {%4,%5,%6,%7}, {%8,%9}, {%0,%1,%2,%3};"
        : "+f"(c[0]), "+f"(c[1]), "+f"(c[2]), "+f"(c[3])
        : "r"(a0), "r"(a1), "r"(a2), "r"(a3), "r"(b0), "r"(b1));
}

// ---------------------------------------------------------------------------
// tf32 tensor-core GEMM:  C[M,N] = A[M,256] @ W[256,N] + bias[N]
// Block tile 128x64, BK=16, 256 threads = 8 warps, warp tile 32x32.
// GATHER=true: A rows are window-partition-gathered image pixels.
// ---------------------------------------------------------------------------
template<bool GATHER>
__global__ __launch_bounds__(256) void gemm_tf32_kernel(
    const float* __restrict__ A, const float* __restrict__ W,
    const float* __restrict__ bias, float* __restrict__ C, int N)
{
    __shared__ uint32_t As[128][20];   // [row][k]  pad->20: conflict-free A frags
    __shared__ uint32_t Wsm[16][68];   // [k][n]    pad->68: <=2-way on B frags
    const int t    = threadIdx.x;
    const int bm   = blockIdx.y, bn = blockIdx.x;
    const int lane = t & 31, warp = t >> 5;
    const int wm   = warp >> 1;        // 0..3  (rows of 32)
    const int wnn  = warp & 1;         // 0..1  (cols of 32)
    const int g    = lane >> 2;        // 0..7
    const int tq   = lane & 3;         // 0..3

    // A staging: thread -> (row t>>1, 8 k-cols at (t&1)*8)
    const int arow = t >> 1, acol = (t & 1) * 8;
    const float* Arow;
    if (GATHER) {
        const int r    = bm * 128 + arow;
        const int wwin = r >> 6, p = r & 63;
        const int b    = wwin >> 8, widx = wwin & 255;
        const int wy   = widx >> 4, wx = widx & 15;
        const int py   = wy * 8 + (p >> 3);
        const int px   = wx * 8 + (p & 7);
        Arow = A + (((size_t)b * IMGH + py) * IMGW + px) * DIM;
    } else {
        Arow = A + (size_t)(bm * 128 + arow) * DIM;
    }
    // W staging: thread -> (k t>>4, 4 n-cols at (t&15)*4)
    const int wk = t >> 4, wn4 = (t & 15) * 4;
    const float* Wp = W + (size_t)wk * N + bn * 64 + wn4;

    float acc[2][4][4];
    #pragma unroll
    for (int mi = 0; mi < 2; mi++)
        #pragma unroll
        for (int ni = 0; ni < 4; ni++)
            #pragma unroll
            for (int j = 0; j < 4; j++) acc[mi][ni][j] = 0.f;

    for (int k0 = 0; k0 < DIM; k0 += 16) {
        float4 a0 = *(const float4*)(Arow + k0 + acol);
        float4 a1 = *(const float4*)(Arow + k0 + acol + 4);
        float4 wv = *(const float4*)(Wp + (size_t)k0 * N);
        As[arow][acol + 0] = f2tf(a0.x);
        As[arow][acol + 1] = f2tf(a0.y);
        As[arow][acol + 2] = f2tf(a0.z);
        As[arow][acol + 3] = f2tf(a0.w);
        As[arow][acol + 4] = f2tf(a1.x);
        As[arow][acol + 5] = f2tf(a1.y);
        As[arow][acol + 6] = f2tf(a1.z);
        As[arow][acol + 7] = f2tf(a1.w);
        Wsm[wk][wn4 + 0] = f2tf(wv.x);
        Wsm[wk][wn4 + 1] = f2tf(wv.y);
        Wsm[wk][wn4 + 2] = f2tf(wv.z);
        Wsm[wk][wn4 + 3] = f2tf(wv.w);
        __syncthreads();

        #pragma unroll
        for (int ks = 0; ks < 16; ks += 8) {
            uint32_t af[2][4], bf[4][2];
            #pragma unroll
            for (int mi = 0; mi < 2; mi++) {
                const int r0 = wm * 32 + mi * 16 + g;
                af[mi][0] = As[r0][ks + tq];
                af[mi][1] = As[r0 + 8][ks + tq];
                af[mi][2] = As[r0][ks + tq + 4];
                af[mi][3] = As[r0 + 8][ks + tq + 4];
            }
            #pragma unroll
            for (int ni = 0; ni < 4; ni++) {
                const int c0 = wnn * 32 + ni * 8 + g;
                bf[ni][0] = Wsm[ks + tq][c0];
                bf[ni][1] = Wsm[ks + tq + 4][c0];
            }
            #pragma unroll
            for (int mi = 0; mi < 2; mi++)
                #pragma unroll
                for (int ni = 0; ni < 4; ni++)
                    mma_tf32(acc[mi][ni], af[mi][0], af[mi][1], af[mi][2], af[mi][3],
                             bf[ni][0], bf[ni][1]);
        }
        __syncthreads();
    }

    // epilogue: bias + store (float2 per mma row-half)
    #pragma unroll
    for (int mi = 0; mi < 2; mi++) {
        const int r0 = bm * 128 + wm * 32 + mi * 16 + g;
        #pragma unroll
        for (int ni = 0; ni < 4; ni++) {
            const int col = bn * 64 + wnn * 32 + ni * 8 + 2 * tq;
            float2 bv = *(const float2*)(bias + col);
            float2 o0 = make_float2(acc[mi][ni][0] + bv.x, acc[mi][ni][1] + bv.y);
            float2 o1 = make_float2(acc[mi][ni][2] + bv.x, acc[mi][ni][3] + bv.y);
            *(float2*)(C + (size_t)r0 * N + col)       = o0;
            *(float2*)(C + (size_t)(r0 + 8) * N + col) = o1;
        }
    }
}

// ---------------------------------------------------------------------------
// Attention: one block per (window, head). 256 threads = 256 queries.
// ---------------------------------------------------------------------------
__global__ __launch_bounds__(256) void attn_kernel(const float* __restrict__ btab)
{
    __shared__ float4 Ks[WS2 * 8];
    __shared__ float4 Vs[WS2 * 8];
    __shared__ float  Bs[WS2][WS2 + 1];

    const int blk = blockIdx.x;
    const int win = blk >> 3;
    const int h   = blk & 7;
    const int t   = threadIdx.x;

    {
        const size_t base = (size_t)win * WS2 * (2 * DIM) + h * HD;
        #pragma unroll
        for (int i = 0; i < 2; i++) {
            int idx = t + i * 256;
            int kr = idx >> 3, dg = idx & 7;
            Ks[idx] = *(const float4*)(g_kv + base + (size_t)kr * 512 + dg * 4);
            Vs[idx] = *(const float4*)(g_kv + base + DIM + (size_t)kr * 512 + dg * 4);
        }
    }
    #pragma unroll
    for (int i = 0; i < 16; i++) {
        int e  = t + i * 256;
        int qp = e >> 6, kp = e & 63;
        int dr = (qp >> 3) - (kp >> 3) + 7;
        int dc = (qp & 7)  - (kp & 7)  + 7;
        Bs[qp][kp] = btab[(dr * 15 + dc) * HEADS + h];
    }
    __syncthreads();

    const float scale = 0.17677669529663687f;
    float4 q4[8];
    {
        const float* qp = g_q + ((size_t)(win * NQ + t)) * DIM + h * HD;
        #pragma unroll
        for (int j = 0; j < 8; j++) {
            float4 v = *(const float4*)(qp + j * 4);
            v.x *= scale; v.y *= scale; v.z *= scale; v.w *= scale;
            q4[j] = v;
        }
    }

    const int qb = t & 63;
    float s[64];
    float mx = -1e30f;
    #pragma unroll
    for (int k = 0; k < 64; k++) {
        float acc = Bs[qb][k];
        #pragma unroll
        for (int j = 0; j < 8; j++) {
            float4 kv = Ks[k * 8 + j];
            acc += q4[j].x * kv.x + q4[j].y * kv.y + q4[j].z * kv.z + q4[j].w * kv.w;
        }
        s[k] = acc;
        mx = fmaxf(mx, acc);
    }
    float sum = 0.f;
    #pragma unroll
    for (int k = 0; k < 64; k++) { float e = __expf(s[k] - mx); s[k] = e; sum += e; }
    const float inv = 1.f / sum;

    float4 o[8];
    #pragma unroll
    for (int j = 0; j < 8; j++) o[j] = make_float4(0.f, 0.f, 0.f, 0.f);
    #pragma unroll
    for (int k = 0; k < 64; k++) {
        float p = s[k];
        #pragma unroll
        for (int j = 0; j < 8; j++) {
            float4 v = Vs[k * 8 + j];
            o[j].x += p * v.x; o[j].y += p * v.y;
            o[j].z += p * v.z; o[j].w += p * v.w;
        }
    }

    float* op = g_att + ((size_t)(win * NQ + t)) * DIM + h * HD;
    #pragma unroll
    for (int j = 0; j < 8; j++) {
        float4 v = o[j];
        v.x *= inv; v.y *= inv; v.z *= inv; v.w *= inv;
        *(float4*)(op + j * 4) = v;
    }
}

// ---------------------------------------------------------------------------
extern "C" void kernel_launch(void* const* d_in, const int* in_sizes, int n_in,
                              void* d_out, int out_size)
{
    const float* gauss = (const float*)d_in[0];
    const float* img   = (const float*)d_in[1];
    const float* btab  = (const float*)d_in[2];
    const float* Wq    = (const float*)d_in[3];
    const float* bq    = (const float*)d_in[4];
    const float* Wkv   = (const float*)d_in[5];
    const float* bkv   = (const float*)d_in[6];
    const float* Wp    = (const float*)d_in[7];
    const float* bp    = (const float*)d_in[8];
    float* out = (float*)d_out;

    void* pq = nullptr;   cudaGetSymbolAddress(&pq, g_q);
    void* pkv = nullptr;  cudaGetSymbolAddress(&pkv, g_kv);
    void* pa = nullptr;   cudaGetSymbolAddress(&pa, g_att);

    // 1) Q projection: [262144,256] @ [256,256] + bq
    gemm_tf32_kernel<false><<<dim3(DIM / 64, ROWS_Q / 128), 256>>>(gauss, Wq, bq, (float*)pq, DIM);
    // 2) KV projection with window gather: [65536,256] @ [256,512] + bkv
    gemm_tf32_kernel<true><<<dim3((2 * DIM) / 64, ROWS_KV / 128), 256>>>(img, Wkv, bkv, (float*)pkv, 2 * DIM);
    // 3) Attention per (window, head)
    attn_kernel<<<BW * HEADS, 256>>>(btab);
    // 4) Output projection: [262144,256] @ [256,256] + bp -> d_out
    gemm_tf32_kernel<false><<<dim3(DIM / 64, ROWS_Q / 128), 256>>>((const float*)pa, Wp, bp, out, DIM);
}